// round 11
// baseline (speedup 1.0000x reference)
#include <cuda_runtime.h>

#define Nn 100000
#define Ee 1600000
#define EPS 1e-5f

// ---------------- device scratch (no allocations allowed) ----------------
// __align__(16) is load-bearing: accessed as float4 / red.global.add.v4.f32.
__device__ __align__(16) float g_sw[Nn * 16];    // segment_sum of w over dst
__device__ __align__(16) float g_deg[Nn];        // in-degree (float)
__device__ __align__(16) float g_h[Nn * 64];     // current normalized+relu h
__device__ __align__(16) float g_bufA[Nn * 64];  // pre-activation buffer
__device__ __align__(16) float g_bufB[Nn * 64];  // scratch (hW / final pre-out)
__device__ __align__(16) float g_stats[8 * 128]; // per-BN: sum[64], sumsq[64]
__device__ __align__(16) float g_ss[8 * 128];    // per-BN: scale[64], shift[64]

// ---------------- helpers ----------------
__device__ __forceinline__ void red_add_v4(float* addr, float4 v) {
    asm volatile("red.global.add.v4.f32 [%0], {%1,%2,%3,%4};"
                 :: "l"(addr), "f"(v.x), "f"(v.y), "f"(v.z), "f"(v.w) : "memory");
}

__device__ __forceinline__ unsigned long long pack2(float x, float y) {
    unsigned long long r;
    asm("mov.b64 %0, {%1,%2};" : "=l"(r) : "f"(x), "f"(y));
    return r;
}

__device__ __forceinline__ float2 unpack2(unsigned long long v) {
    float2 r;
    asm("mov.b64 {%0,%1}, %2;" : "=f"(r.x), "=f"(r.y) : "l"(v));
    return r;
}

__device__ __forceinline__ void fma2(unsigned long long& d, unsigned long long a,
                                     unsigned long long b) {
    asm("fma.rn.f32x2 %0, %1, %2, %0;" : "+l"(d) : "l"(a), "l"(b));
}

// acc[32] (packed pairs of 64 outputs) += a * Wrow[0..63]
__device__ __forceinline__ void fma_row(unsigned long long* acc, float a,
                                        const float* wrow) {
    unsigned long long aa = pack2(a, a);
    const ulonglong2* wp = reinterpret_cast<const ulonglong2*>(wrow);
#pragma unroll
    for (int j = 0; j < 16; j++) {
        ulonglong2 v = wp[j];
        fma2(acc[2 * j], aa, v.x);
        fma2(acc[2 * j + 1], aa, v.y);
    }
}

// ---------------- kernels ----------------
__global__ void k_zero() {
    int i = blockIdx.x * blockDim.x + threadIdx.x;
    int stride = gridDim.x * blockDim.x;
    for (int j = i; j < Nn * 16; j += stride) g_sw[j] = 0.f;
    for (int j = i; j < Nn; j += stride) g_deg[j] = 0.f;
    if (i < 8 * 128) g_stats[i] = 0.f;
}

// sw[dst] += w[e];  deg[dst] += 1
__global__ __launch_bounds__(256) void k_scatter_w(const float* __restrict__ w,
                                                   const int* __restrict__ dst) {
    int t = blockIdx.x * blockDim.x + threadIdx.x;
    if (t >= Ee * 4) return;
    int e = t >> 2, q = t & 3;
    int d = __ldg(&dst[e]);
    float4 wv = __ldg(&reinterpret_cast<const float4*>(w)[e * 4 + q]);
    red_add_v4(&g_sw[(size_t)d * 16 + q * 4], wv);
    if (q == 0) atomicAdd(&g_deg[d], 1.0f);
}

// bufA = x@aW + ab + sw@bW0 + deg*bb0
__global__ __launch_bounds__(128) void k_layer0(const float* __restrict__ x,
                                                const float* __restrict__ aW,
                                                const float* __restrict__ ab,
                                                const float* __restrict__ bW0,
                                                const float* __restrict__ bb0) {
    __shared__ __align__(16) float Wa[64 * 64];
    __shared__ __align__(16) float Wb[16 * 64];
    __shared__ float absh[64], bb0sh[64];
    int tid = threadIdx.x;
    for (int i = tid; i < 1024; i += 128)
        reinterpret_cast<float4*>(Wa)[i] = reinterpret_cast<const float4*>(aW)[i];
    for (int i = tid; i < 256; i += 128)
        reinterpret_cast<float4*>(Wb)[i] = reinterpret_cast<const float4*>(bW0)[i];
    if (tid < 64) { absh[tid] = ab[tid]; bb0sh[tid] = bb0[tid]; }
    __syncthreads();
    int n = blockIdx.x * 128 + tid;
    if (n >= Nn) return;
    float degv = g_deg[n];
    unsigned long long acc[32];
#pragma unroll
    for (int j = 0; j < 32; j++)
        acc[j] = pack2(absh[2 * j] + degv * bb0sh[2 * j],
                       absh[2 * j + 1] + degv * bb0sh[2 * j + 1]);
    const float4* xr = reinterpret_cast<const float4*>(x + (size_t)n * 64);
#pragma unroll
    for (int k0 = 0; k0 < 16; k0++) {
        float4 v = xr[k0];
        fma_row(acc, v.x, Wa + (k0 * 4 + 0) * 64);
        fma_row(acc, v.y, Wa + (k0 * 4 + 1) * 64);
        fma_row(acc, v.z, Wa + (k0 * 4 + 2) * 64);
        fma_row(acc, v.w, Wa + (k0 * 4 + 3) * 64);
    }
    const float4* swr = reinterpret_cast<const float4*>(g_sw + (size_t)n * 16);
#pragma unroll
    for (int k0 = 0; k0 < 4; k0++) {
        float4 v = swr[k0];
        fma_row(acc, v.x, Wb + (k0 * 4 + 0) * 64);
        fma_row(acc, v.y, Wb + (k0 * 4 + 1) * 64);
        fma_row(acc, v.z, Wb + (k0 * 4 + 2) * 64);
        fma_row(acc, v.w, Wb + (k0 * 4 + 3) * 64);
    }
    float4* outr = reinterpret_cast<float4*>(g_bufA + (size_t)n * 64);
#pragma unroll
    for (int j = 0; j < 16; j++) {
        float2 a = unpack2(acc[2 * j]);
        float2 b = unpack2(acc[2 * j + 1]);
        outr[j] = make_float4(a.x, a.y, b.x, b.y);
    }
}

// Fused per-layer prologue (strict per-row ownership => safe fusion):
//   h = relu(bn(bufA));  g_h = h;  bufB = h @ W;
//   bufA = sw@bW + deg*bb + h1b          (scatter-init, overwrites bufA row)
__global__ __launch_bounds__(128) void k_g1i1(const float* __restrict__ W, int ssid,
                                              const float* __restrict__ bW,
                                              const float* __restrict__ bb,
                                              const float* __restrict__ h1b) {
    __shared__ __align__(16) float Ws[64 * 64];
    __shared__ __align__(16) float Wb[16 * 64];
    __shared__ float scs[64], shs[64], bbsh[64], h1bsh[64];
    int tid = threadIdx.x;
    for (int i = tid; i < 1024; i += 128)
        reinterpret_cast<float4*>(Ws)[i] = reinterpret_cast<const float4*>(W)[i];
    for (int i = tid; i < 256; i += 128)
        reinterpret_cast<float4*>(Wb)[i] = reinterpret_cast<const float4*>(bW)[i];
    if (tid < 64) {
        scs[tid] = g_ss[ssid * 128 + tid];
        shs[tid] = g_ss[ssid * 128 + 64 + tid];
        bbsh[tid] = bb[tid];
        h1bsh[tid] = h1b[tid];
    }
    __syncthreads();
    int n = blockIdx.x * 128 + tid;
    if (n >= Nn) return;

    // --- part 1: h = relu(bn(bufA)), bufB = h@W ---
    unsigned long long acc[32];
#pragma unroll
    for (int j = 0; j < 32; j++) acc[j] = pack2(0.f, 0.f);
    const float4* inr = reinterpret_cast<const float4*>(g_bufA + (size_t)n * 64);
    float4* hout = reinterpret_cast<float4*>(g_h + (size_t)n * 64);
#pragma unroll
    for (int k0 = 0; k0 < 16; k0++) {
        float4 v = inr[k0];
        int f = k0 * 4;
        v.x = fmaxf(fmaf(v.x, scs[f + 0], shs[f + 0]), 0.f);
        v.y = fmaxf(fmaf(v.y, scs[f + 1], shs[f + 1]), 0.f);
        v.z = fmaxf(fmaf(v.z, scs[f + 2], shs[f + 2]), 0.f);
        v.w = fmaxf(fmaf(v.w, scs[f + 3], shs[f + 3]), 0.f);
        hout[k0] = v;
        fma_row(acc, v.x, Ws + (f + 0) * 64);
        fma_row(acc, v.y, Ws + (f + 1) * 64);
        fma_row(acc, v.z, Ws + (f + 2) * 64);
        fma_row(acc, v.w, Ws + (f + 3) * 64);
    }
    float4* outr = reinterpret_cast<float4*>(g_bufB + (size_t)n * 64);
#pragma unroll
    for (int j = 0; j < 16; j++) {
        float2 a = unpack2(acc[2 * j]);
        float2 b = unpack2(acc[2 * j + 1]);
        outr[j] = make_float4(a.x, a.y, b.x, b.y);
    }

    // --- part 2: bufA row = sw@bW + deg*bb + h1b (this thread owns the row) ---
    float sws[16];
    {
        const float4* swr = reinterpret_cast<const float4*>(g_sw + (size_t)n * 16);
#pragma unroll
        for (int k0 = 0; k0 < 4; k0++) {
            float4 s = swr[k0];
            sws[k0 * 4 + 0] = s.x; sws[k0 * 4 + 1] = s.y;
            sws[k0 * 4 + 2] = s.z; sws[k0 * 4 + 3] = s.w;
        }
    }
    float degv = g_deg[n];
    float4* ar = reinterpret_cast<float4*>(g_bufA + (size_t)n * 64);
#pragma unroll
    for (int j = 0; j < 16; j++) {
        int f = j * 4;
        float4 a4 = make_float4(h1bsh[f + 0] + degv * bbsh[f + 0],
                                h1bsh[f + 1] + degv * bbsh[f + 1],
                                h1bsh[f + 2] + degv * bbsh[f + 2],
                                h1bsh[f + 3] + degv * bbsh[f + 3]);
#pragma unroll
        for (int k = 0; k < 16; k++) {
            float4 wv = *reinterpret_cast<const float4*>(&Wb[k * 64 + f]);
            a4.x += sws[k] * wv.x;
            a4.y += sws[k] * wv.y;
            a4.z += sws[k] * wv.z;
            a4.w += sws[k] * wv.w;
        }
        ar[j] = a4;
    }
}

// bufA[dst] += bufB[src]   (16 threads per edge, float4 reductions)
__global__ __launch_bounds__(256) void k_scatter_h(const int* __restrict__ src,
                                                   const int* __restrict__ dst) {
    int t = blockIdx.x * 256 + threadIdx.x;  // Ee*16 = 25.6M fits int
    int e = t >> 4, q = t & 15;
    int s = __ldg(&src[e]);
    int d = __ldg(&dst[e]);
    float4 v = __ldg(reinterpret_cast<const float4*>(g_bufB + (size_t)s * 64 + q * 4));
    red_add_v4(g_bufA + (size_t)d * 64 + q * 4, v);
}

// per-feature sum / sumsq over nodes -> g_stats[id]
__global__ __launch_bounds__(256) void k_stats(int which, int id) {
    const float* buf = which ? g_bufB : g_bufA;
    int f = threadIdx.x & 63;
    int rl = threadIdx.x >> 6;
    float s = 0.f, sq = 0.f;
    for (int row = blockIdx.x * 4 + rl; row < Nn; row += gridDim.x * 4) {
        float v = buf[(size_t)row * 64 + f];
        s += v;
        sq += v * v;
    }
    __shared__ float ssum[64], ssq[64];
    if (threadIdx.x < 64) { ssum[threadIdx.x] = 0.f; ssq[threadIdx.x] = 0.f; }
    __syncthreads();
    atomicAdd(&ssum[f], s);
    atomicAdd(&ssq[f], sq);
    __syncthreads();
    if (threadIdx.x < 64) {
        atomicAdd(&g_stats[id * 128 + threadIdx.x], ssum[threadIdx.x]);
        atomicAdd(&g_stats[id * 128 + 64 + threadIdx.x], ssq[threadIdx.x]);
    }
}

// scale/shift from stats
__global__ void k_fin(int id, const float* __restrict__ g, const float* __restrict__ be) {
    int j = threadIdx.x;
    if (j >= 64) return;
    float inv = 1.0f / (float)Nn;
    float mean = g_stats[id * 128 + j] * inv;
    float var = g_stats[id * 128 + 64 + j] * inv - mean * mean;
    var = fmaxf(var, 0.f);
    float sc = g[j] * rsqrtf(var + EPS);
    g_ss[id * 128 + j] = sc;
    g_ss[id * 128 + 64 + j] = be[j] - mean * sc;
}

// bufA = relu(bn(bufA)) @ W + bias + g_h   (in-place per-row)
__global__ __launch_bounds__(128) void k_g2(const float* __restrict__ W,
                                            const float* __restrict__ bias, int ssid) {
    __shared__ __align__(16) float Ws[64 * 64];
    __shared__ float scs[64], shs[64], bsh[64];
    int tid = threadIdx.x;
    for (int i = tid; i < 1024; i += 128)
        reinterpret_cast<float4*>(Ws)[i] = reinterpret_cast<const float4*>(W)[i];
    if (tid < 64) {
        scs[tid] = g_ss[ssid * 128 + tid];
        shs[tid] = g_ss[ssid * 128 + 64 + tid];
        bsh[tid] = bias[tid];
    }
    __syncthreads();
    int n = blockIdx.x * 128 + tid;
    if (n >= Nn) return;
    unsigned long long acc[32];
#pragma unroll
    for (int j = 0; j < 32; j++) acc[j] = pack2(bsh[2 * j], bsh[2 * j + 1]);
    const float4* inr = reinterpret_cast<const float4*>(g_bufA + (size_t)n * 64);
#pragma unroll
    for (int k0 = 0; k0 < 16; k0++) {
        float4 v = inr[k0];
        int f = k0 * 4;
        v.x = fmaxf(fmaf(v.x, scs[f + 0], shs[f + 0]), 0.f);
        v.y = fmaxf(fmaf(v.y, scs[f + 1], shs[f + 1]), 0.f);
        v.z = fmaxf(fmaf(v.z, scs[f + 2], shs[f + 2]), 0.f);
        v.w = fmaxf(fmaf(v.w, scs[f + 3], shs[f + 3]), 0.f);
        fma_row(acc, v.x, Ws + (f + 0) * 64);
        fma_row(acc, v.y, Ws + (f + 1) * 64);
        fma_row(acc, v.z, Ws + (f + 2) * 64);
        fma_row(acc, v.w, Ws + (f + 3) * 64);
    }
    const float4* hres = reinterpret_cast<const float4*>(g_h + (size_t)n * 64);
    float4* outr = reinterpret_cast<float4*>(g_bufA + (size_t)n * 64);
#pragma unroll
    for (int j = 0; j < 16; j++) {
        float2 a = unpack2(acc[2 * j]);
        float2 b = unpack2(acc[2 * j + 1]);
        float4 r = hres[j];
        outr[j] = make_float4(a.x + r.x, a.y + r.y, b.x + r.z, b.y + r.w);
    }
}

// bufB = relu(bn(bufA)) @ lW + lb
__global__ __launch_bounds__(128) void k_final(const float* __restrict__ W,
                                               const float* __restrict__ bias, int ssid) {
    __shared__ __align__(16) float Ws[64 * 64];
    __shared__ float scs[64], shs[64], bsh[64];
    int tid = threadIdx.x;
    for (int i = tid; i < 1024; i += 128)
        reinterpret_cast<float4*>(Ws)[i] = reinterpret_cast<const float4*>(W)[i];
    if (tid < 64) {
        scs[tid] = g_ss[ssid * 128 + tid];
        shs[tid] = g_ss[ssid * 128 + 64 + tid];
        bsh[tid] = bias[tid];
    }
    __syncthreads();
    int n = blockIdx.x * 128 + tid;
    if (n >= Nn) return;
    unsigned long long acc[32];
#pragma unroll
    for (int j = 0; j < 32; j++) acc[j] = pack2(bsh[2 * j], bsh[2 * j + 1]);
    const float4* inr = reinterpret_cast<const float4*>(g_bufA + (size_t)n * 64);
#pragma unroll
    for (int k0 = 0; k0 < 16; k0++) {
        float4 v = inr[k0];
        int f = k0 * 4;
        v.x = fmaxf(fmaf(v.x, scs[f + 0], shs[f + 0]), 0.f);
        v.y = fmaxf(fmaf(v.y, scs[f + 1], shs[f + 1]), 0.f);
        v.z = fmaxf(fmaf(v.z, scs[f + 2], shs[f + 2]), 0.f);
        v.w = fmaxf(fmaf(v.w, scs[f + 3], shs[f + 3]), 0.f);
        fma_row(acc, v.x, Ws + (f + 0) * 64);
        fma_row(acc, v.y, Ws + (f + 1) * 64);
        fma_row(acc, v.z, Ws + (f + 2) * 64);
        fma_row(acc, v.w, Ws + (f + 3) * 64);
    }
    float4* outr = reinterpret_cast<float4*>(g_bufB + (size_t)n * 64);
#pragma unroll
    for (int j = 0; j < 16; j++) {
        float2 a = unpack2(acc[2 * j]);
        float2 b = unpack2(acc[2 * j + 1]);
        outr[j] = make_float4(a.x, a.y, b.x, b.y);
    }
}

// out = bn(bufB)   (no relu)
__global__ __launch_bounds__(256) void k_out(float* __restrict__ out, int id) {
    int t = blockIdx.x * 256 + threadIdx.x;
    if (t >= Nn * 16) return;
    int q = t & 15;
    int f = q * 4;
    float4 v = reinterpret_cast<const float4*>(g_bufB)[t];
    v.x = fmaf(v.x, g_ss[id * 128 + f + 0], g_ss[id * 128 + 64 + f + 0]);
    v.y = fmaf(v.y, g_ss[id * 128 + f + 1], g_ss[id * 128 + 64 + f + 1]);
    v.z = fmaf(v.z, g_ss[id * 128 + f + 2], g_ss[id * 128 + 64 + f + 2]);
    v.w = fmaf(v.w, g_ss[id * 128 + f + 3], g_ss[id * 128 + 64 + f + 3]);
    reinterpret_cast<float4*>(out)[t] = v;
}

// ---------------- launch ----------------
extern "C" void kernel_launch(void* const* d_in, const int* in_sizes, int n_in,
                              void* d_out, int out_size) {
    const float* x    = (const float*)d_in[0];
    const float* w    = (const float*)d_in[1];
    const int*   src  = (const int*)d_in[2];
    const int*   dst  = (const int*)d_in[3];
    const float* aW   = (const float*)d_in[4];
    const float* ab   = (const float*)d_in[5];
    const float* bW0  = (const float*)d_in[6];
    const float* bb0  = (const float*)d_in[7];
    const float* g0   = (const float*)d_in[8];
    const float* be0  = (const float*)d_in[9];
    const float* bWs  = (const float*)d_in[10];
    const float* bbs  = (const float*)d_in[11];
    const float* h1W  = (const float*)d_in[12];
    const float* h1b  = (const float*)d_in[13];
    const float* h2W  = (const float*)d_in[14];
    const float* h2b  = (const float*)d_in[15];
    const float* g1s  = (const float*)d_in[16];
    const float* be1s = (const float*)d_in[17];
    const float* g2s  = (const float*)d_in[18];
    const float* be2s = (const float*)d_in[19];
    const float* lW   = (const float*)d_in[20];
    const float* lb   = (const float*)d_in[21];
    const float* gl   = (const float*)d_in[22];
    const float* bel  = (const float*)d_in[23];

    k_zero<<<2048, 256>>>();
    k_scatter_w<<<(Ee * 4) / 256, 256>>>(w, dst);
    k_layer0<<<(Nn + 127) / 128, 128>>>(x, aW, ab, bW0, bb0);
    k_stats<<<512, 256>>>(0, 0);
    k_fin<<<1, 64>>>(0, g0, be0);

    for (int i = 0; i < 3; i++) {
        int prev = (i == 0) ? 0 : 2 * i;
        k_g1i1<<<(Nn + 127) / 128, 128>>>(h1W + (size_t)i * 4096, prev,
                                          bWs + (size_t)i * 1024,
                                          bbs + (size_t)i * 64,
                                          h1b + (size_t)i * 64);
        k_scatter_h<<<(Ee * 16) / 256, 256>>>(src, dst);
        k_stats<<<512, 256>>>(0, 2 * i + 1);
        k_fin<<<1, 64>>>(2 * i + 1, g1s + (size_t)i * 64, be1s + (size_t)i * 64);
        k_g2<<<(Nn + 127) / 128, 128>>>(h2W + (size_t)i * 4096,
                                        h2b + (size_t)i * 64, 2 * i + 1);
        k_stats<<<512, 256>>>(0, 2 * i + 2);
        k_fin<<<1, 64>>>(2 * i + 2, g2s + (size_t)i * 64, be2s + (size_t)i * 64);
    }

    k_final<<<(Nn + 127) / 128, 128>>>(lW, lb, 6);
    k_stats<<<512, 256>>>(1, 7);
    k_fin<<<1, 64>>>(7, gl, bel);
    k_out<<<(Nn * 16 + 255) / 256, 256>>>((float*)d_out, 7);
}

// round 12
// speedup vs baseline: 1.8111x; 1.8111x over previous
#include <cuda_runtime.h>

#define Nn 100000
#define Ee 1600000
#define EPS 1e-5f
#define NCHUNK ((Nn + 255) / 256)   // 391
#define STATS_GRID 1024

// ---------------- device scratch (no allocations allowed) ----------------
__device__ __align__(16) float g_sw[Nn * 16];
__device__ __align__(16) float g_deg[Nn];
__device__ __align__(16) float g_h[Nn * 64];
__device__ __align__(16) float g_bufA[Nn * 64];
__device__ __align__(16) float g_bufB[Nn * 64];
__device__ __align__(16) float g_stats[8 * 128];
__device__ __align__(16) float g_ss[8 * 128];
// CSR structures (built per launch)
__device__ int g_degi[Nn];
__device__ int g_chunk[NCHUNK];
__device__ int g_chunkoff[NCHUNK];
__device__ int g_rowptr[Nn + 1];
__device__ int g_cursor[Nn];
__device__ int g_csr[Ee];

// ---------------- helpers ----------------
__device__ __forceinline__ void red_add_v4(float* addr, float4 v) {
    asm volatile("red.global.add.v4.f32 [%0], {%1,%2,%3,%4};"
                 :: "l"(addr), "f"(v.x), "f"(v.y), "f"(v.z), "f"(v.w) : "memory");
}

__device__ __forceinline__ unsigned long long pack2(float x, float y) {
    unsigned long long r;
    asm("mov.b64 %0, {%1,%2};" : "=l"(r) : "f"(x), "f"(y));
    return r;
}

__device__ __forceinline__ float2 unpack2(unsigned long long v) {
    float2 r;
    asm("mov.b64 {%0,%1}, %2;" : "=f"(r.x), "=f"(r.y) : "l"(v));
    return r;
}

__device__ __forceinline__ void fma2(unsigned long long& d, unsigned long long a,
                                     unsigned long long b) {
    asm("fma.rn.f32x2 %0, %1, %2, %0;" : "+l"(d) : "l"(a), "l"(b));
}

__device__ __forceinline__ void fma_row(unsigned long long* acc, float a,
                                        const float* wrow) {
    unsigned long long aa = pack2(a, a);
    const ulonglong2* wp = reinterpret_cast<const ulonglong2*>(wrow);
#pragma unroll
    for (int j = 0; j < 16; j++) {
        ulonglong2 v = wp[j];
        fma2(acc[2 * j], aa, v.x);
        fma2(acc[2 * j + 1], aa, v.y);
    }
}

// ---------------- kernels ----------------
__global__ void k_zero() {
    int i = blockIdx.x * blockDim.x + threadIdx.x;
    int stride = gridDim.x * blockDim.x;
    for (int j = i; j < Nn * 16; j += stride) g_sw[j] = 0.f;
    for (int j = i; j < Nn; j += stride) g_degi[j] = 0;
    if (i < 8 * 128) g_stats[i] = 0.f;
}

// sw[dst] += w[e];  degi[dst] += 1
__global__ __launch_bounds__(256) void k_scatter_w(const float* __restrict__ w,
                                                   const int* __restrict__ dst) {
    int t = blockIdx.x * blockDim.x + threadIdx.x;
    if (t >= Ee * 4) return;
    int e = t >> 2, q = t & 3;
    int d = __ldg(&dst[e]);
    float4 wv = __ldg(&reinterpret_cast<const float4*>(w)[e * 4 + q]);
    red_add_v4(&g_sw[(size_t)d * 16 + q * 4], wv);
    if (q == 0) atomicAdd(&g_degi[d], 1);
}

// ---- CSR build: chunk sums -> chunk scan -> rowptr/cursor -> fill ----
__global__ __launch_bounds__(256) void k_chunksum() {
    __shared__ int s[256];
    int n = blockIdx.x * 256 + threadIdx.x;
    s[threadIdx.x] = (n < Nn) ? g_degi[n] : 0;
    __syncthreads();
    for (int off = 128; off > 0; off >>= 1) {
        if (threadIdx.x < off) s[threadIdx.x] += s[threadIdx.x + off];
        __syncthreads();
    }
    if (threadIdx.x == 0) g_chunk[blockIdx.x] = s[0];
}

__global__ __launch_bounds__(512) void k_chunkscan() {
    __shared__ int s[512];
    int tid = threadIdx.x;
    int myv = (tid < NCHUNK) ? g_chunk[tid] : 0;
    s[tid] = myv;
    __syncthreads();
    for (int off = 1; off < 512; off <<= 1) {
        int v = (tid >= off) ? s[tid - off] : 0;
        __syncthreads();
        s[tid] += v;
        __syncthreads();
    }
    if (tid < NCHUNK) g_chunkoff[tid] = s[tid] - myv;  // exclusive
    if (tid == 511) g_rowptr[Nn] = s[511];             // total == Ee
}

__global__ __launch_bounds__(256) void k_rowptr() {
    __shared__ int s[256];
    int tid = threadIdx.x;
    int n = blockIdx.x * 256 + tid;
    int d = (n < Nn) ? g_degi[n] : 0;
    s[tid] = d;
    __syncthreads();
    for (int off = 1; off < 256; off <<= 1) {
        int v = (tid >= off) ? s[tid - off] : 0;
        __syncthreads();
        s[tid] += v;
        __syncthreads();
    }
    if (n < Nn) {
        int start = g_chunkoff[blockIdx.x] + s[tid] - d;  // exclusive scan
        g_rowptr[n] = start;
        g_cursor[n] = start;
        g_deg[n] = (float)d;
    }
}

__global__ __launch_bounds__(256) void k_fill(const int* __restrict__ src,
                                              const int* __restrict__ dst) {
    int t = blockIdx.x * 256 + threadIdx.x;
    if (t >= Ee) return;
    int d = __ldg(&dst[t]);
    int pos = atomicAdd(&g_cursor[d], 1);
    g_csr[pos] = __ldg(&src[t]);
}

// bufA = x@aW + ab + sw@bW0 + deg*bb0
__global__ __launch_bounds__(128) void k_layer0(const float* __restrict__ x,
                                                const float* __restrict__ aW,
                                                const float* __restrict__ ab,
                                                const float* __restrict__ bW0,
                                                const float* __restrict__ bb0) {
    __shared__ __align__(16) float Wa[64 * 64];
    __shared__ __align__(16) float Wb[16 * 64];
    __shared__ float absh[64], bb0sh[64];
    int tid = threadIdx.x;
    for (int i = tid; i < 1024; i += 128)
        reinterpret_cast<float4*>(Wa)[i] = reinterpret_cast<const float4*>(aW)[i];
    for (int i = tid; i < 256; i += 128)
        reinterpret_cast<float4*>(Wb)[i] = reinterpret_cast<const float4*>(bW0)[i];
    if (tid < 64) { absh[tid] = ab[tid]; bb0sh[tid] = bb0[tid]; }
    __syncthreads();
    int n = blockIdx.x * 128 + tid;
    if (n >= Nn) return;
    float degv = g_deg[n];
    unsigned long long acc[32];
#pragma unroll
    for (int j = 0; j < 32; j++)
        acc[j] = pack2(absh[2 * j] + degv * bb0sh[2 * j],
                       absh[2 * j + 1] + degv * bb0sh[2 * j + 1]);
    const float4* xr = reinterpret_cast<const float4*>(x + (size_t)n * 64);
#pragma unroll
    for (int k0 = 0; k0 < 16; k0++) {
        float4 v = xr[k0];
        fma_row(acc, v.x, Wa + (k0 * 4 + 0) * 64);
        fma_row(acc, v.y, Wa + (k0 * 4 + 1) * 64);
        fma_row(acc, v.z, Wa + (k0 * 4 + 2) * 64);
        fma_row(acc, v.w, Wa + (k0 * 4 + 3) * 64);
    }
    const float4* swr = reinterpret_cast<const float4*>(g_sw + (size_t)n * 16);
#pragma unroll
    for (int k0 = 0; k0 < 4; k0++) {
        float4 v = swr[k0];
        fma_row(acc, v.x, Wb + (k0 * 4 + 0) * 64);
        fma_row(acc, v.y, Wb + (k0 * 4 + 1) * 64);
        fma_row(acc, v.z, Wb + (k0 * 4 + 2) * 64);
        fma_row(acc, v.w, Wb + (k0 * 4 + 3) * 64);
    }
    float4* outr = reinterpret_cast<float4*>(g_bufA + (size_t)n * 64);
#pragma unroll
    for (int j = 0; j < 16; j++) {
        float2 a = unpack2(acc[2 * j]);
        float2 b = unpack2(acc[2 * j + 1]);
        outr[j] = make_float4(a.x, a.y, b.x, b.y);
    }
}

// Fused per-layer prologue:
//   h = relu(bn(bufA));  g_h = h;  bufB = h @ W;
//   bufA = sw@bW + deg*bb + h1b
__global__ __launch_bounds__(128) void k_g1i1(const float* __restrict__ W, int ssid,
                                              const float* __restrict__ bW,
                                              const float* __restrict__ bb,
                                              const float* __restrict__ h1b) {
    __shared__ __align__(16) float Ws[64 * 64];
    __shared__ __align__(16) float Wb[16 * 64];
    __shared__ float scs[64], shs[64], bbsh[64], h1bsh[64];
    int tid = threadIdx.x;
    for (int i = tid; i < 1024; i += 128)
        reinterpret_cast<float4*>(Ws)[i] = reinterpret_cast<const float4*>(W)[i];
    for (int i = tid; i < 256; i += 128)
        reinterpret_cast<float4*>(Wb)[i] = reinterpret_cast<const float4*>(bW)[i];
    if (tid < 64) {
        scs[tid] = g_ss[ssid * 128 + tid];
        shs[tid] = g_ss[ssid * 128 + 64 + tid];
        bbsh[tid] = bb[tid];
        h1bsh[tid] = h1b[tid];
    }
    __syncthreads();
    int n = blockIdx.x * 128 + tid;
    if (n >= Nn) return;

    unsigned long long acc[32];
#pragma unroll
    for (int j = 0; j < 32; j++) acc[j] = pack2(0.f, 0.f);
    const float4* inr = reinterpret_cast<const float4*>(g_bufA + (size_t)n * 64);
    float4* hout = reinterpret_cast<float4*>(g_h + (size_t)n * 64);
#pragma unroll
    for (int k0 = 0; k0 < 16; k0++) {
        float4 v = inr[k0];
        int f = k0 * 4;
        v.x = fmaxf(fmaf(v.x, scs[f + 0], shs[f + 0]), 0.f);
        v.y = fmaxf(fmaf(v.y, scs[f + 1], shs[f + 1]), 0.f);
        v.z = fmaxf(fmaf(v.z, scs[f + 2], shs[f + 2]), 0.f);
        v.w = fmaxf(fmaf(v.w, scs[f + 3], shs[f + 3]), 0.f);
        hout[k0] = v;
        fma_row(acc, v.x, Ws + (f + 0) * 64);
        fma_row(acc, v.y, Ws + (f + 1) * 64);
        fma_row(acc, v.z, Ws + (f + 2) * 64);
        fma_row(acc, v.w, Ws + (f + 3) * 64);
    }
    float4* outr = reinterpret_cast<float4*>(g_bufB + (size_t)n * 64);
#pragma unroll
    for (int j = 0; j < 16; j++) {
        float2 a = unpack2(acc[2 * j]);
        float2 b = unpack2(acc[2 * j + 1]);
        outr[j] = make_float4(a.x, a.y, b.x, b.y);
    }

    float sws[16];
    {
        const float4* swr = reinterpret_cast<const float4*>(g_sw + (size_t)n * 16);
#pragma unroll
        for (int k0 = 0; k0 < 4; k0++) {
            float4 s = swr[k0];
            sws[k0 * 4 + 0] = s.x; sws[k0 * 4 + 1] = s.y;
            sws[k0 * 4 + 2] = s.z; sws[k0 * 4 + 3] = s.w;
        }
    }
    float degv = g_deg[n];
    float4* ar = reinterpret_cast<float4*>(g_bufA + (size_t)n * 64);
#pragma unroll
    for (int j = 0; j < 16; j++) {
        int f = j * 4;
        float4 a4 = make_float4(h1bsh[f + 0] + degv * bbsh[f + 0],
                                h1bsh[f + 1] + degv * bbsh[f + 1],
                                h1bsh[f + 2] + degv * bbsh[f + 2],
                                h1bsh[f + 3] + degv * bbsh[f + 3]);
#pragma unroll
        for (int k = 0; k < 16; k++) {
            float4 wv = *reinterpret_cast<const float4*>(&Wb[k * 64 + f]);
            a4.x += sws[k] * wv.x;
            a4.y += sws[k] * wv.y;
            a4.z += sws[k] * wv.z;
            a4.w += sws[k] * wv.w;
        }
        ar[j] = a4;
    }
}

// pull-mode gather: bufA[n] += sum_{k in rowptr[n]..rowptr[n+1]} bufB[csr[k]]
// 16 threads per node (one float4 quad each); no atomics.
__global__ __launch_bounds__(256) void k_gather() {
    int t = blockIdx.x * 256 + threadIdx.x;
    if (t >= Nn * 16) return;
    int n = t >> 4, q = t & 15;
    int start = __ldg(&g_rowptr[n]);
    int end = __ldg(&g_rowptr[n + 1]);
    const float4* bb = reinterpret_cast<const float4*>(g_bufB);
    float4 acc = reinterpret_cast<const float4*>(g_bufA)[t];
    int k = start;
    for (; k + 4 <= end; k += 4) {
        int s0 = __ldg(&g_csr[k + 0]);
        int s1 = __ldg(&g_csr[k + 1]);
        int s2 = __ldg(&g_csr[k + 2]);
        int s3 = __ldg(&g_csr[k + 3]);
        float4 v0 = __ldg(&bb[s0 * 16 + q]);
        float4 v1 = __ldg(&bb[s1 * 16 + q]);
        float4 v2 = __ldg(&bb[s2 * 16 + q]);
        float4 v3 = __ldg(&bb[s3 * 16 + q]);
        acc.x += v0.x + v1.x + v2.x + v3.x;
        acc.y += v0.y + v1.y + v2.y + v3.y;
        acc.z += v0.z + v1.z + v2.z + v3.z;
        acc.w += v0.w + v1.w + v2.w + v3.w;
    }
    for (; k < end; k++) {
        int s = __ldg(&g_csr[k]);
        float4 v = __ldg(&bb[s * 16 + q]);
        acc.x += v.x; acc.y += v.y; acc.z += v.z; acc.w += v.w;
    }
    reinterpret_cast<float4*>(g_bufA)[t] = acc;
}

// vectorized per-feature stats: sum/sumsq over nodes -> g_stats[id]
__global__ __launch_bounds__(256) void k_stats(int which, int id) {
    const float4* buf = reinterpret_cast<const float4*>(which ? g_bufB : g_bufA);
    int tid = threadIdx.x;
    int t0 = blockIdx.x * 256 + tid;
    int f = (t0 & 15) * 4;  // invariant: stride (STATS_GRID*256) % 16 == 0
    float4 s = make_float4(0.f, 0.f, 0.f, 0.f);
    float4 sq = make_float4(0.f, 0.f, 0.f, 0.f);
    for (int t = t0; t < Nn * 16; t += STATS_GRID * 256) {
        float4 v = __ldg(&buf[t]);
        s.x += v.x; s.y += v.y; s.z += v.z; s.w += v.w;
        sq.x += v.x * v.x; sq.y += v.y * v.y;
        sq.z += v.z * v.z; sq.w += v.w * v.w;
    }
    __shared__ float ssum[64], ssq[64];
    if (tid < 64) { ssum[tid] = 0.f; ssq[tid] = 0.f; }
    __syncthreads();
    atomicAdd(&ssum[f + 0], s.x); atomicAdd(&ssum[f + 1], s.y);
    atomicAdd(&ssum[f + 2], s.z); atomicAdd(&ssum[f + 3], s.w);
    atomicAdd(&ssq[f + 0], sq.x); atomicAdd(&ssq[f + 1], sq.y);
    atomicAdd(&ssq[f + 2], sq.z); atomicAdd(&ssq[f + 3], sq.w);
    __syncthreads();
    if (tid < 64) {
        atomicAdd(&g_stats[id * 128 + tid], ssum[tid]);
        atomicAdd(&g_stats[id * 128 + 64 + tid], ssq[tid]);
    }
}

// scale/shift from stats
__global__ void k_fin(int id, const float* __restrict__ g, const float* __restrict__ be) {
    int j = threadIdx.x;
    if (j >= 64) return;
    float inv = 1.0f / (float)Nn;
    float mean = g_stats[id * 128 + j] * inv;
    float var = g_stats[id * 128 + 64 + j] * inv - mean * mean;
    var = fmaxf(var, 0.f);
    float sc = g[j] * rsqrtf(var + EPS);
    g_ss[id * 128 + j] = sc;
    g_ss[id * 128 + 64 + j] = be[j] - mean * sc;
}

// bufA = relu(bn(bufA)) @ W + bias + g_h
__global__ __launch_bounds__(128) void k_g2(const float* __restrict__ W,
                                            const float* __restrict__ bias, int ssid) {
    __shared__ __align__(16) float Ws[64 * 64];
    __shared__ float scs[64], shs[64], bsh[64];
    int tid = threadIdx.x;
    for (int i = tid; i < 1024; i += 128)
        reinterpret_cast<float4*>(Ws)[i] = reinterpret_cast<const float4*>(W)[i];
    if (tid < 64) {
        scs[tid] = g_ss[ssid * 128 + tid];
        shs[tid] = g_ss[ssid * 128 + 64 + tid];
        bsh[tid] = bias[tid];
    }
    __syncthreads();
    int n = blockIdx.x * 128 + tid;
    if (n >= Nn) return;
    unsigned long long acc[32];
#pragma unroll
    for (int j = 0; j < 32; j++) acc[j] = pack2(bsh[2 * j], bsh[2 * j + 1]);
    const float4* inr = reinterpret_cast<const float4*>(g_bufA + (size_t)n * 64);
#pragma unroll
    for (int k0 = 0; k0 < 16; k0++) {
        float4 v = inr[k0];
        int f = k0 * 4;
        v.x = fmaxf(fmaf(v.x, scs[f + 0], shs[f + 0]), 0.f);
        v.y = fmaxf(fmaf(v.y, scs[f + 1], shs[f + 1]), 0.f);
        v.z = fmaxf(fmaf(v.z, scs[f + 2], shs[f + 2]), 0.f);
        v.w = fmaxf(fmaf(v.w, scs[f + 3], shs[f + 3]), 0.f);
        fma_row(acc, v.x, Ws + (f + 0) * 64);
        fma_row(acc, v.y, Ws + (f + 1) * 64);
        fma_row(acc, v.z, Ws + (f + 2) * 64);
        fma_row(acc, v.w, Ws + (f + 3) * 64);
    }
    const float4* hres = reinterpret_cast<const float4*>(g_h + (size_t)n * 64);
    float4* outr = reinterpret_cast<float4*>(g_bufA + (size_t)n * 64);
#pragma unroll
    for (int j = 0; j < 16; j++) {
        float2 a = unpack2(acc[2 * j]);
        float2 b = unpack2(acc[2 * j + 1]);
        float4 r = hres[j];
        outr[j] = make_float4(a.x + r.x, a.y + r.y, b.x + r.z, b.y + r.w);
    }
}

// bufB = relu(bn(bufA)) @ lW + lb
__global__ __launch_bounds__(128) void k_final(const float* __restrict__ W,
                                               const float* __restrict__ bias, int ssid) {
    __shared__ __align__(16) float Ws[64 * 64];
    __shared__ float scs[64], shs[64], bsh[64];
    int tid = threadIdx.x;
    for (int i = tid; i < 1024; i += 128)
        reinterpret_cast<float4*>(Ws)[i] = reinterpret_cast<const float4*>(W)[i];
    if (tid < 64) {
        scs[tid] = g_ss[ssid * 128 + tid];
        shs[tid] = g_ss[ssid * 128 + 64 + tid];
        bsh[tid] = bias[tid];
    }
    __syncthreads();
    int n = blockIdx.x * 128 + tid;
    if (n >= Nn) return;
    unsigned long long acc[32];
#pragma unroll
    for (int j = 0; j < 32; j++) acc[j] = pack2(bsh[2 * j], bsh[2 * j + 1]);
    const float4* inr = reinterpret_cast<const float4*>(g_bufA + (size_t)n * 64);
#pragma unroll
    for (int k0 = 0; k0 < 16; k0++) {
        float4 v = inr[k0];
        int f = k0 * 4;
        v.x = fmaxf(fmaf(v.x, scs[f + 0], shs[f + 0]), 0.f);
        v.y = fmaxf(fmaf(v.y, scs[f + 1], shs[f + 1]), 0.f);
        v.z = fmaxf(fmaf(v.z, scs[f + 2], shs[f + 2]), 0.f);
        v.w = fmaxf(fmaf(v.w, scs[f + 3], shs[f + 3]), 0.f);
        fma_row(acc, v.x, Ws + (f + 0) * 64);
        fma_row(acc, v.y, Ws + (f + 1) * 64);
        fma_row(acc, v.z, Ws + (f + 2) * 64);
        fma_row(acc, v.w, Ws + (f + 3) * 64);
    }
    float4* outr = reinterpret_cast<float4*>(g_bufB + (size_t)n * 64);
#pragma unroll
    for (int j = 0; j < 16; j++) {
        float2 a = unpack2(acc[2 * j]);
        float2 b = unpack2(acc[2 * j + 1]);
        outr[j] = make_float4(a.x, a.y, b.x, b.y);
    }
}

// out = bn(bufB)
__global__ __launch_bounds__(256) void k_out(float* __restrict__ out, int id) {
    int t = blockIdx.x * 256 + threadIdx.x;
    if (t >= Nn * 16) return;
    int q = t & 15;
    int f = q * 4;
    float4 v = reinterpret_cast<const float4*>(g_bufB)[t];
    v.x = fmaf(v.x, g_ss[id * 128 + f + 0], g_ss[id * 128 + 64 + f + 0]);
    v.y = fmaf(v.y, g_ss[id * 128 + f + 1], g_ss[id * 128 + 64 + f + 1]);
    v.z = fmaf(v.z, g_ss[id * 128 + f + 2], g_ss[id * 128 + 64 + f + 2]);
    v.w = fmaf(v.w, g_ss[id * 128 + f + 3], g_ss[id * 128 + 64 + f + 3]);
    reinterpret_cast<float4*>(out)[t] = v;
}

// ---------------- launch ----------------
extern "C" void kernel_launch(void* const* d_in, const int* in_sizes, int n_in,
                              void* d_out, int out_size) {
    const float* x    = (const float*)d_in[0];
    const float* w    = (const float*)d_in[1];
    const int*   src  = (const int*)d_in[2];
    const int*   dst  = (const int*)d_in[3];
    const float* aW   = (const float*)d_in[4];
    const float* ab   = (const float*)d_in[5];
    const float* bW0  = (const float*)d_in[6];
    const float* bb0  = (const float*)d_in[7];
    const float* g0   = (const float*)d_in[8];
    const float* be0  = (const float*)d_in[9];
    const float* bWs  = (const float*)d_in[10];
    const float* bbs  = (const float*)d_in[11];
    const float* h1W  = (const float*)d_in[12];
    const float* h1b  = (const float*)d_in[13];
    const float* h2W  = (const float*)d_in[14];
    const float* h2b  = (const float*)d_in[15];
    const float* g1s  = (const float*)d_in[16];
    const float* be1s = (const float*)d_in[17];
    const float* g2s  = (const float*)d_in[18];
    const float* be2s = (const float*)d_in[19];
    const float* lW   = (const float*)d_in[20];
    const float* lb   = (const float*)d_in[21];
    const float* gl   = (const float*)d_in[22];
    const float* bel  = (const float*)d_in[23];

    k_zero<<<2048, 256>>>();
    k_scatter_w<<<(Ee * 4) / 256, 256>>>(w, dst);
    // CSR build
    k_chunksum<<<NCHUNK, 256>>>();
    k_chunkscan<<<1, 512>>>();
    k_rowptr<<<NCHUNK, 256>>>();
    k_fill<<<(Ee + 255) / 256, 256>>>(src, dst);

    k_layer0<<<(Nn + 127) / 128, 128>>>(x, aW, ab, bW0, bb0);
    k_stats<<<STATS_GRID, 256>>>(0, 0);
    k_fin<<<1, 64>>>(0, g0, be0);

    for (int i = 0; i < 3; i++) {
        int prev = (i == 0) ? 0 : 2 * i;
        k_g1i1<<<(Nn + 127) / 128, 128>>>(h1W + (size_t)i * 4096, prev,
                                          bWs + (size_t)i * 1024,
                                          bbs + (size_t)i * 64,
                                          h1b + (size_t)i * 64);
        k_gather<<<(Nn * 16 + 255) / 256, 256>>>();
        k_stats<<<STATS_GRID, 256>>>(0, 2 * i + 1);
        k_fin<<<1, 64>>>(2 * i + 1, g1s + (size_t)i * 64, be1s + (size_t)i * 64);
        k_g2<<<(Nn + 127) / 128, 128>>>(h2W + (size_t)i * 4096,
                                        h2b + (size_t)i * 64, 2 * i + 1);
        k_stats<<<STATS_GRID, 256>>>(0, 2 * i + 2);
        k_fin<<<1, 64>>>(2 * i + 2, g2s + (size_t)i * 64, be2s + (size_t)i * 64);
    }

    k_final<<<(Nn + 127) / 128, 128>>>(lW, lb, 6);
    k_stats<<<STATS_GRID, 256>>>(1, 7);
    k_fin<<<1, 64>>>(7, gl, bel);
    k_out<<<(Nn * 16 + 255) / 256, 256>>>((float*)d_out, 7);
}